// round 4
// baseline (speedup 1.0000x reference)
#include <cuda_runtime.h>
#include <cstdint>

#define NF 128          // node feature dim F
#define EFD 7           // edge feature dim
#define NMAX 100000     // node count

// Scratch for h = nfeat @ W.T + b  (51.2 MB)
__device__ float g_h[(size_t)NMAX * NF];

// ---------------------------------------------------------------------------
// Kernel A: h = nfeat @ W.T + b ; out = relu(h + root_emb) / degs ; store h
// Scalar-FFMA tiled SGEMM (fastest measured variant).
// ---------------------------------------------------------------------------
#define BM 128
#define BK 16

__global__ void __launch_bounds__(256)
gemm_h_kernel(const float* __restrict__ A,      // nfeat [N,128]
              const float* __restrict__ W,      // [128,128]
              const float* __restrict__ bvec,   // [128]
              const float* __restrict__ root,   // [1,128]
              const float* __restrict__ degs,   // [N]
              float* __restrict__ hout,         // [N,128]
              float* __restrict__ out,          // [N,128]
              int N)
{
    __shared__ float sA[BK][BM];      // [k][m]
    __shared__ float sW[BK][NF];      // [k][j] = W[j][kc+k]

    const int tid = threadIdx.x;           // 0..255
    const int tx  = tid & 15;              // col group
    const int ty  = tid >> 4;              // row group
    const int m0  = blockIdx.x * BM;

    float acc[8][8];
#pragma unroll
    for (int i = 0; i < 8; i++)
#pragma unroll
        for (int j = 0; j < 8; j++) acc[i][j] = 0.f;

    float bj[8], rj[8];
#pragma unroll
    for (int j = 0; j < 8; j++) {
        bj[j] = __ldg(bvec + tx * 8 + j);
        rj[j] = __ldg(root + tx * 8 + j);
    }

    for (int kc = 0; kc < NF; kc += BK) {
#pragma unroll
        for (int i = 0; i < 2; i++) {
            int r = (tid >> 2) + i * 64;
            int c = (tid & 3) * 4;
            float4 v = make_float4(0.f, 0.f, 0.f, 0.f);
            int gr = m0 + r;
            if (gr < N)
                v = *reinterpret_cast<const float4*>(A + (size_t)gr * NF + kc + c);
            sA[c + 0][r] = v.x; sA[c + 1][r] = v.y;
            sA[c + 2][r] = v.z; sA[c + 3][r] = v.w;
        }
#pragma unroll
        for (int i = 0; i < 2; i++) {
            int j = (tid >> 2) + i * 64;
            int c = (tid & 3) * 4;
            float4 v = *reinterpret_cast<const float4*>(W + (size_t)j * NF + kc + c);
            sW[c + 0][j] = v.x; sW[c + 1][j] = v.y;
            sW[c + 2][j] = v.z; sW[c + 3][j] = v.w;
        }
        __syncthreads();

#pragma unroll
        for (int k = 0; k < BK; k++) {
            float a[8], w[8];
#pragma unroll
            for (int i = 0; i < 8; i += 4) {
                *reinterpret_cast<float4*>(&a[i]) =
                    *reinterpret_cast<const float4*>(&sA[k][ty * 8 + i]);
                *reinterpret_cast<float4*>(&w[i]) =
                    *reinterpret_cast<const float4*>(&sW[k][tx * 8 + i]);
            }
#pragma unroll
            for (int i = 0; i < 8; i++)
#pragma unroll
                for (int j = 0; j < 8; j++)
                    acc[i][j] = fmaf(a[i], w[j], acc[i][j]);
        }
        __syncthreads();
    }

#pragma unroll
    for (int i = 0; i < 8; i++) {
        int m = m0 + ty * 8 + i;
        if (m < N) {
            float invd = 1.0f / degs[m];
#pragma unroll
            for (int j4 = 0; j4 < 8; j4 += 4) {
                int j = tx * 8 + j4;
                float4 hv, ov;
                hv.x = acc[i][j4 + 0] + bj[j4 + 0];
                hv.y = acc[i][j4 + 1] + bj[j4 + 1];
                hv.z = acc[i][j4 + 2] + bj[j4 + 2];
                hv.w = acc[i][j4 + 3] + bj[j4 + 3];
                ov.x = fmaxf(hv.x + rj[j4 + 0], 0.f) * invd;
                ov.y = fmaxf(hv.y + rj[j4 + 1], 0.f) * invd;
                ov.z = fmaxf(hv.z + rj[j4 + 2], 0.f) * invd;
                ov.w = fmaxf(hv.w + rj[j4 + 3], 0.f) * invd;
                *reinterpret_cast<float4*>(hout + (size_t)m * NF + j) = hv;
                *reinterpret_cast<float4*>(out  + (size_t)m * NF + j) = ov;
            }
        }
    }
}

// ---------------------------------------------------------------------------
// Kernel B: 8 edges per warp per iteration.
//   - efeat for the 8 edges (56 floats) loaded by lanes 0..13 in ONE LDG.128,
//     then distributed via compile-time-indexed warp shuffles (no registers
//     burnt on a 56-float array, no L1 wavefronts for the reads).
//   - all 8 h[src] gathers in flight before any consumption.
//   - red.global.add.v4.f32 scatter.
// ---------------------------------------------------------------------------
__global__ void __launch_bounds__(256, 3)
edge_kernel(const float* __restrict__ efeat,   // [E,7]
            const float* __restrict__ norm,    // [E]
            const int*   __restrict__ src,
            const int*   __restrict__ dst,
            const float* __restrict__ We,      // [128,7]
            const float* __restrict__ be,      // [128]
            const float* __restrict__ h,       // [N,128]
            float* __restrict__ out,           // [N,128]
            int E)
{
    const int lane = threadIdx.x & 31;
    const int j0   = lane * 4;  // this lane's 4 output features

    // register-cache this lane's slice of We / be
    float w[4][EFD], bias[4];
#pragma unroll
    for (int j = 0; j < 4; j++) {
        bias[j] = __ldg(be + j0 + j);
#pragma unroll
        for (int k = 0; k < EFD; k++)
            w[j][k] = __ldg(We + (size_t)(j0 + j) * EFD + k);
    }

    const int warp_id = (blockIdx.x * blockDim.x + threadIdx.x) >> 5;
    const int nwarps  = (gridDim.x * blockDim.x) >> 5;
    const int Emain   = E & ~7;

    for (int e0 = warp_id * 8; e0 < Emain; e0 += nwarps * 8) {
        // src indices first — issue all 8 gathers ASAP
        const int4 sa = __ldcs(reinterpret_cast<const int4*>(src + e0));
        const int4 sb = __ldcs(reinterpret_cast<const int4*>(src + e0 + 4));

        float4 hv[8];
        hv[0] = *reinterpret_cast<const float4*>(h + (size_t)sa.x * NF + j0);
        hv[1] = *reinterpret_cast<const float4*>(h + (size_t)sa.y * NF + j0);
        hv[2] = *reinterpret_cast<const float4*>(h + (size_t)sa.z * NF + j0);
        hv[3] = *reinterpret_cast<const float4*>(h + (size_t)sa.w * NF + j0);
        hv[4] = *reinterpret_cast<const float4*>(h + (size_t)sb.x * NF + j0);
        hv[5] = *reinterpret_cast<const float4*>(h + (size_t)sb.y * NF + j0);
        hv[6] = *reinterpret_cast<const float4*>(h + (size_t)sb.z * NF + j0);
        hv[7] = *reinterpret_cast<const float4*>(h + (size_t)sb.w * NF + j0);

        // lane-parallel efeat load: 56 floats = 14 float4, lanes 0..13
        float ld0 = 0.f, ld1 = 0.f, ld2 = 0.f, ld3 = 0.f;
        if (lane < 14) {
            float4 t = __ldcs(reinterpret_cast<const float4*>(
                              efeat + (size_t)e0 * EFD) + lane);
            ld0 = t.x; ld1 = t.y; ld2 = t.z; ld3 = t.w;
        }

        const int4   da = __ldcs(reinterpret_cast<const int4*>(dst + e0));
        const int4   db = __ldcs(reinterpret_cast<const int4*>(dst + e0 + 4));
        const float4 na = __ldcs(reinterpret_cast<const float4*>(norm + e0));
        const float4 nb = __ldcs(reinterpret_cast<const float4*>(norm + e0 + 4));

        const int   d[8]  = {da.x, da.y, da.z, da.w, db.x, db.y, db.z, db.w};
        const float nr[8] = {na.x, na.y, na.z, na.w, nb.x, nb.y, nb.z, nb.w};

#pragma unroll
        for (int u = 0; u < 8; u++) {
            float v0 = bias[0], v1 = bias[1], v2 = bias[2], v3 = bias[3];
#pragma unroll
            for (int k = 0; k < EFD; k++) {
                const int idx = u * EFD + k;           // compile-time
                float src_val;
                switch (idx & 3) {
                    case 0: src_val = ld0; break;
                    case 1: src_val = ld1; break;
                    case 2: src_val = ld2; break;
                    default: src_val = ld3; break;
                }
                float x = __shfl_sync(0xffffffffu, src_val, idx >> 2);
                v0 = fmaf(w[0][k], x, v0);
                v1 = fmaf(w[1][k], x, v1);
                v2 = fmaf(w[2][k], x, v2);
                v3 = fmaf(w[3][k], x, v3);
            }
            v0 = fmaxf(hv[u].x + v0, 0.f) * nr[u];
            v1 = fmaxf(hv[u].y + v1, 0.f) * nr[u];
            v2 = fmaxf(hv[u].z + v2, 0.f) * nr[u];
            v3 = fmaxf(hv[u].w + v3, 0.f) * nr[u];

            float* p = out + (size_t)d[u] * NF + j0;
            asm volatile("red.global.add.v4.f32 [%0], {%1, %2, %3, %4};"
                         :: "l"(p), "f"(v0), "f"(v1), "f"(v2), "f"(v3)
                         : "memory");
        }
    }

    // tail (E not multiple of 8) — handled by warp 0
    if (warp_id == 0) {
        for (int e = Emain; e < E; e++) {
            const int   se = __ldg(src + e);
            const int   de = __ldg(dst + e);
            const float nre = __ldg(norm + e);
            float efs[EFD];
#pragma unroll
            for (int k = 0; k < EFD; k++)
                efs[k] = __ldg(efeat + (size_t)e * EFD + k);
            float4 hvv = *reinterpret_cast<const float4*>(h + (size_t)se * NF + j0);
            float v0 = bias[0], v1 = bias[1], v2 = bias[2], v3 = bias[3];
#pragma unroll
            for (int k = 0; k < EFD; k++) {
                v0 = fmaf(w[0][k], efs[k], v0);
                v1 = fmaf(w[1][k], efs[k], v1);
                v2 = fmaf(w[2][k], efs[k], v2);
                v3 = fmaf(w[3][k], efs[k], v3);
            }
            v0 = fmaxf(hvv.x + v0, 0.f) * nre;
            v1 = fmaxf(hvv.y + v1, 0.f) * nre;
            v2 = fmaxf(hvv.z + v2, 0.f) * nre;
            v3 = fmaxf(hvv.w + v3, 0.f) * nre;
            float* p = out + (size_t)de * NF + j0;
            asm volatile("red.global.add.v4.f32 [%0], {%1, %2, %3, %4};"
                         :: "l"(p), "f"(v0), "f"(v1), "f"(v2), "f"(v3)
                         : "memory");
        }
    }
}

// ---------------------------------------------------------------------------
// Launch.  Input order: nfeat, efeat, degs, norm, src, dst, W, b, We, be, root
// ---------------------------------------------------------------------------
extern "C" void kernel_launch(void* const* d_in, const int* in_sizes, int n_in,
                              void* d_out, int out_size)
{
    const float* nfeat = (const float*)d_in[0];
    const float* efeat = (const float*)d_in[1];
    const float* degs  = (const float*)d_in[2];
    const float* norm  = (const float*)d_in[3];
    const int*   src   = (const int*)  d_in[4];
    const int*   dst   = (const int*)  d_in[5];
    const float* W     = (const float*)d_in[6];
    const float* b     = (const float*)d_in[7];
    const float* We    = (const float*)d_in[8];
    const float* be    = (const float*)d_in[9];
    const float* root  = (const float*)d_in[10];
    float* out = (float*)d_out;

    const int N = in_sizes[0] / NF;
    const int E = in_sizes[4];

    float* h;
    cudaGetSymbolAddress((void**)&h, g_h);

    int gridA = (N + BM - 1) / BM;
    gemm_h_kernel<<<gridA, 256>>>(nfeat, W, b, root, degs, h, out, N);

    int gridB = 1480;
    edge_kernel<<<gridB, 256>>>(efeat, norm, src, dst, We, be, h, out, E);
}

// round 5
// speedup vs baseline: 2.1851x; 2.1851x over previous
#include <cuda_runtime.h>
#include <cstdint>

#define NF 128          // node feature dim F
#define EFD 7           // edge feature dim
#define NMAX 100000     // node count

// Scratch for h = nfeat @ W.T + b  (51.2 MB)
__device__ float g_h[(size_t)NMAX * NF];

// ---------------------------------------------------------------------------
// Kernel A: h = nfeat @ W.T + b ; out = relu(h + root_emb) / degs ; store h
// Scalar-FFMA tiled SGEMM (fastest measured variant, ~105us).
// ---------------------------------------------------------------------------
#define BM 128
#define BK 16

__global__ void __launch_bounds__(256)
gemm_h_kernel(const float* __restrict__ A,      // nfeat [N,128]
              const float* __restrict__ W,      // [128,128]
              const float* __restrict__ bvec,   // [128]
              const float* __restrict__ root,   // [1,128]
              const float* __restrict__ degs,   // [N]
              float* __restrict__ hout,         // [N,128]
              float* __restrict__ out,          // [N,128]
              int N)
{
    __shared__ float sA[BK][BM];      // [k][m]
    __shared__ float sW[BK][NF];      // [k][j] = W[j][kc+k]

    const int tid = threadIdx.x;           // 0..255
    const int tx  = tid & 15;              // col group
    const int ty  = tid >> 4;              // row group
    const int m0  = blockIdx.x * BM;

    float acc[8][8];
#pragma unroll
    for (int i = 0; i < 8; i++)
#pragma unroll
        for (int j = 0; j < 8; j++) acc[i][j] = 0.f;

    float bj[8], rj[8];
#pragma unroll
    for (int j = 0; j < 8; j++) {
        bj[j] = __ldg(bvec + tx * 8 + j);
        rj[j] = __ldg(root + tx * 8 + j);
    }

    for (int kc = 0; kc < NF; kc += BK) {
#pragma unroll
        for (int i = 0; i < 2; i++) {
            int r = (tid >> 2) + i * 64;
            int c = (tid & 3) * 4;
            float4 v = make_float4(0.f, 0.f, 0.f, 0.f);
            int gr = m0 + r;
            if (gr < N)
                v = *reinterpret_cast<const float4*>(A + (size_t)gr * NF + kc + c);
            sA[c + 0][r] = v.x; sA[c + 1][r] = v.y;
            sA[c + 2][r] = v.z; sA[c + 3][r] = v.w;
        }
#pragma unroll
        for (int i = 0; i < 2; i++) {
            int j = (tid >> 2) + i * 64;
            int c = (tid & 3) * 4;
            float4 v = *reinterpret_cast<const float4*>(W + (size_t)j * NF + kc + c);
            sW[c + 0][j] = v.x; sW[c + 1][j] = v.y;
            sW[c + 2][j] = v.z; sW[c + 3][j] = v.w;
        }
        __syncthreads();

#pragma unroll
        for (int k = 0; k < BK; k++) {
            float a[8], w[8];
#pragma unroll
            for (int i = 0; i < 8; i += 4) {
                *reinterpret_cast<float4*>(&a[i]) =
                    *reinterpret_cast<const float4*>(&sA[k][ty * 8 + i]);
                *reinterpret_cast<float4*>(&w[i]) =
                    *reinterpret_cast<const float4*>(&sW[k][tx * 8 + i]);
            }
#pragma unroll
            for (int i = 0; i < 8; i++)
#pragma unroll
                for (int j = 0; j < 8; j++)
                    acc[i][j] = fmaf(a[i], w[j], acc[i][j]);
        }
        __syncthreads();
    }

#pragma unroll
    for (int i = 0; i < 8; i++) {
        int m = m0 + ty * 8 + i;
        if (m < N) {
            float invd = 1.0f / degs[m];
#pragma unroll
            for (int j4 = 0; j4 < 8; j4 += 4) {
                int j = tx * 8 + j4;
                float4 hv, ov;
                hv.x = acc[i][j4 + 0] + bj[j4 + 0];
                hv.y = acc[i][j4 + 1] + bj[j4 + 1];
                hv.z = acc[i][j4 + 2] + bj[j4 + 2];
                hv.w = acc[i][j4 + 3] + bj[j4 + 3];
                ov.x = fmaxf(hv.x + rj[j4 + 0], 0.f) * invd;
                ov.y = fmaxf(hv.y + rj[j4 + 1], 0.f) * invd;
                ov.z = fmaxf(hv.z + rj[j4 + 2], 0.f) * invd;
                ov.w = fmaxf(hv.w + rj[j4 + 3], 0.f) * invd;
                *reinterpret_cast<float4*>(hout + (size_t)m * NF + j) = hv;
                *reinterpret_cast<float4*>(out  + (size_t)m * NF + j) = ov;
            }
        }
    }
}

// ---------------------------------------------------------------------------
// Kernel B (R3 design, measured 175us): 8 edges per warp per iteration.
// All 8 h[src] gathers issued before any consumption. efeat held in a
// register array (56 floats) loaded via 14 uniform LDG.128 (all parallel).
// Streaming inputs use __ldcs. red.global.add.v4.f32 scatter.
// ---------------------------------------------------------------------------
__global__ void __launch_bounds__(256)
edge_kernel(const float* __restrict__ efeat,   // [E,7]
            const float* __restrict__ norm,    // [E]
            const int*   __restrict__ src,
            const int*   __restrict__ dst,
            const float* __restrict__ We,      // [128,7]
            const float* __restrict__ be,      // [128]
            const float* __restrict__ h,       // [N,128]
            float* __restrict__ out,           // [N,128]
            int E)
{
    const int lane = threadIdx.x & 31;
    const int j0   = lane * 4;  // this lane's 4 output features

    // register-cache this lane's slice of We / be
    float w[4][EFD], bias[4];
#pragma unroll
    for (int j = 0; j < 4; j++) {
        bias[j] = __ldg(be + j0 + j);
#pragma unroll
        for (int k = 0; k < EFD; k++)
            w[j][k] = __ldg(We + (size_t)(j0 + j) * EFD + k);
    }

    const int warp_id = (blockIdx.x * blockDim.x + threadIdx.x) >> 5;
    const int nwarps  = (gridDim.x * blockDim.x) >> 5;
    const int Emain   = E & ~7;

    for (int e0 = warp_id * 8; e0 < Emain; e0 += nwarps * 8) {
        // uniform vector loads for 8 consecutive edges (streaming)
        const int4   sa = __ldcs(reinterpret_cast<const int4*>(src + e0));
        const int4   sb = __ldcs(reinterpret_cast<const int4*>(src + e0 + 4));
        const int4   da = __ldcs(reinterpret_cast<const int4*>(dst + e0));
        const int4   db = __ldcs(reinterpret_cast<const int4*>(dst + e0 + 4));
        const float4 na = __ldcs(reinterpret_cast<const float4*>(norm + e0));
        const float4 nb = __ldcs(reinterpret_cast<const float4*>(norm + e0 + 4));

        const int s[8] = {sa.x, sa.y, sa.z, sa.w, sb.x, sb.y, sb.z, sb.w};
        const int d[8] = {da.x, da.y, da.z, da.w, db.x, db.y, db.z, db.w};
        const float nr[8] = {na.x, na.y, na.z, na.w, nb.x, nb.y, nb.z, nb.w};

        // all 8 gathers in flight before any consume
        float4 hv[8];
#pragma unroll
        for (int u = 0; u < 8; u++)
            hv[u] = *reinterpret_cast<const float4*>(h + (size_t)s[u] * NF + j0);

        // efeat: 8 edges x 7 feats = 56 floats = 14 aligned float4 (streaming)
        float ef[56];
#pragma unroll
        for (int q = 0; q < 14; q++)
            *reinterpret_cast<float4*>(&ef[q * 4]) =
                __ldcs(reinterpret_cast<const float4*>(efeat + (size_t)e0 * EFD + q * 4));

#pragma unroll
        for (int u = 0; u < 8; u++) {
            float v0 = bias[0], v1 = bias[1], v2 = bias[2], v3 = bias[3];
#pragma unroll
            for (int k = 0; k < EFD; k++) {
                float x = ef[u * EFD + k];
                v0 = fmaf(w[0][k], x, v0);
                v1 = fmaf(w[1][k], x, v1);
                v2 = fmaf(w[2][k], x, v2);
                v3 = fmaf(w[3][k], x, v3);
            }
            v0 = fmaxf(hv[u].x + v0, 0.f) * nr[u];
            v1 = fmaxf(hv[u].y + v1, 0.f) * nr[u];
            v2 = fmaxf(hv[u].z + v2, 0.f) * nr[u];
            v3 = fmaxf(hv[u].w + v3, 0.f) * nr[u];

            float* p = out + (size_t)d[u] * NF + j0;
            asm volatile("red.global.add.v4.f32 [%0], {%1, %2, %3, %4};"
                         :: "l"(p), "f"(v0), "f"(v1), "f"(v2), "f"(v3)
                         : "memory");
        }
    }

    // tail (E not multiple of 8) — handled by warp 0
    if (warp_id == 0) {
        for (int e = Emain; e < E; e++) {
            const int   se = __ldg(src + e);
            const int   de = __ldg(dst + e);
            const float nre = __ldg(norm + e);
            float efs[EFD];
#pragma unroll
            for (int k = 0; k < EFD; k++)
                efs[k] = __ldg(efeat + (size_t)e * EFD + k);
            float4 hvv = *reinterpret_cast<const float4*>(h + (size_t)se * NF + j0);
            float v0 = bias[0], v1 = bias[1], v2 = bias[2], v3 = bias[3];
#pragma unroll
            for (int k = 0; k < EFD; k++) {
                v0 = fmaf(w[0][k], efs[k], v0);
                v1 = fmaf(w[1][k], efs[k], v1);
                v2 = fmaf(w[2][k], efs[k], v2);
                v3 = fmaf(w[3][k], efs[k], v3);
            }
            v0 = fmaxf(hvv.x + v0, 0.f) * nre;
            v1 = fmaxf(hvv.y + v1, 0.f) * nre;
            v2 = fmaxf(hvv.z + v2, 0.f) * nre;
            v3 = fmaxf(hvv.w + v3, 0.f) * nre;
            float* p = out + (size_t)de * NF + j0;
            asm volatile("red.global.add.v4.f32 [%0], {%1, %2, %3, %4};"
                         :: "l"(p), "f"(v0), "f"(v1), "f"(v2), "f"(v3)
                         : "memory");
        }
    }
}

// ---------------------------------------------------------------------------
// Launch.  Input order: nfeat, efeat, degs, norm, src, dst, W, b, We, be, root
// ---------------------------------------------------------------------------
extern "C" void kernel_launch(void* const* d_in, const int* in_sizes, int n_in,
                              void* d_out, int out_size)
{
    const float* nfeat = (const float*)d_in[0];
    const float* efeat = (const float*)d_in[1];
    const float* degs  = (const float*)d_in[2];
    const float* norm  = (const float*)d_in[3];
    const int*   src   = (const int*)  d_in[4];
    const int*   dst   = (const int*)  d_in[5];
    const float* W     = (const float*)d_in[6];
    const float* b     = (const float*)d_in[7];
    const float* We    = (const float*)d_in[8];
    const float* be    = (const float*)d_in[9];
    const float* root  = (const float*)d_in[10];
    float* out = (float*)d_out;

    const int N = in_sizes[0] / NF;
    const int E = in_sizes[4];

    float* h;
    cudaGetSymbolAddress((void**)&h, g_h);

    int gridA = (N + BM - 1) / BM;
    gemm_h_kernel<<<gridA, 256>>>(nfeat, W, b, root, degs, h, out, N);

    int gridB = 1480;
    edge_kernel<<<gridB, 256>>>(efeat, norm, src, dst, We, be, h, out, E);
}